// round 4
// baseline (speedup 1.0000x reference)
#include <cuda_runtime.h>
#include <math.h>

#define H 1024
#define V 50257
#define L 512
#define NB_LOGIT ((V + 7) / 8)   // 6283 blocks of 8 rows in k_logits
#define NLC 16                   // l-chunks in attn-apply partial stage

// ---------------- scratch (device globals; no allocations allowed) ----------
__device__ float g_s[L];              // raw attention scores
__device__ float g_part[NLC * H];     // partial attn_applied sums
__device__ float g_comb[2 * H];       // [embedded | attn_applied]
__device__ float g_x[H];              // relu(combined @ Wc^T + bc)
__device__ float g_h[H];              // h_new
__device__ float g_logits[V];
__device__ float g_pm[NB_LOGIT];      // per-block max
__device__ float g_ps[NB_LOGIT];      // per-block sum exp

__inline__ __device__ float warpSum(float v) {
    #pragma unroll
    for (int o = 16; o; o >>= 1) v += __shfl_xor_sync(0xffffffffu, v, o);
    return v;
}
__inline__ __device__ float warpMax(float v) {
    #pragma unroll
    for (int o = 16; o; o >>= 1) v = fmaxf(v, __shfl_xor_sync(0xffffffffu, v, o));
    return v;
}

// K1: s[l] = dot(h0, enc[l]); warp-per-row, 64 blocks x 256
__global__ void k_scores(const float* __restrict__ hid, const float* __restrict__ enc) {
    __shared__ float4 hs[H / 4];
    int t = threadIdx.x;
    hs[t] = ((const float4*)hid)[t];
    __syncthreads();
    int warp = t >> 5, lane = t & 31;
    int l = blockIdx.x * 8 + warp;
    const float4* e4 = (const float4*)(enc + (size_t)l * H);
    float acc = 0.f;
    #pragma unroll
    for (int k = 0; k < 8; k++) {
        float4 a = e4[lane + 32 * k], b = hs[lane + 32 * k];
        acc += a.x * b.x + a.y * b.y + a.z * b.z + a.w * b.w;
    }
    acc = warpSum(acc);
    if (lane == 0) g_s[l] = acc;
}

// K2: fused softmax (recomputed per block from g_s) + partial attn apply.
// grid 64 = 4 h-chunks x 16 l-chunks; block 256.
__global__ void k_attnps(const float* __restrict__ enc, float* __restrict__ out_attn) {
    __shared__ float ws[L];
    __shared__ float red[8];
    __shared__ float bcast;
    int t = threadIdx.x;
    int hc = blockIdx.x & 3;
    int lc = blockIdx.x >> 2;

    float s0 = g_s[t], s1 = g_s[t + 256];
    // block max
    float m = warpMax(fmaxf(s0, s1));
    if ((t & 31) == 0) red[t >> 5] = m;
    __syncthreads();
    if (t == 0) {
        float mm = red[0];
        #pragma unroll
        for (int i = 1; i < 8; i++) mm = fmaxf(mm, red[i]);
        bcast = mm;
    }
    __syncthreads();
    float M = bcast;
    float e0 = expf(s0 - M), e1 = expf(s1 - M);
    __syncthreads();
    // block sum
    float s = warpSum(e0 + e1);
    if ((t & 31) == 0) red[t >> 5] = s;
    __syncthreads();
    if (t == 0) {
        float ss = 0.f;
        #pragma unroll
        for (int i = 0; i < 8; i++) ss += red[i];
        bcast = 1.f / ss;
    }
    __syncthreads();
    float inv = bcast;
    ws[t] = e0 * inv;
    ws[t + 256] = e1 * inv;
    __syncthreads();

    if (hc == 0 && t < 32) out_attn[lc * 32 + t] = ws[lc * 32 + t];

    int h = hc * 256 + t;
    const float* ep = enc + (size_t)(lc * 32) * H + h;
    float acc = 0.f;
    #pragma unroll
    for (int l = 0; l < 32; l++) acc += ws[lc * 32 + l] * ep[(size_t)l * H];
    g_part[lc * H + h] = acc;
}

// K3: reduce partials -> combined[H..2H); embedded gather -> combined[0..H)
__global__ void k_attnr(const float* __restrict__ emb, const long long* __restrict__ tok) {
    int h = blockIdx.x * 256 + threadIdx.x;
    float a = 0.f;
    #pragma unroll
    for (int i = 0; i < NLC; i++) a += g_part[i * H + h];
    g_comb[H + h] = a;
    g_comb[h] = emb[(size_t)tok[0] * H + h];
}

// K4: x[row] = relu(dot(Wc[row], combined)+bc); warp-per-row, 128 blocks x 256
__global__ void k_combine(const float* __restrict__ wc, const float* __restrict__ bc) {
    __shared__ float4 cs[2 * H / 4];
    int t = threadIdx.x;
    cs[t] = ((const float4*)g_comb)[t];
    cs[t + 256] = ((const float4*)g_comb)[t + 256];
    __syncthreads();
    int warp = t >> 5, lane = t & 31;
    int row = blockIdx.x * 8 + warp;
    const float4* w4 = (const float4*)(wc + (size_t)row * 2 * H);
    float acc = 0.f;
    #pragma unroll
    for (int k = 0; k < 16; k++) {
        float4 a = w4[lane + 32 * k], b = cs[lane + 32 * k];
        acc += a.x * b.x + a.y * b.y + a.z * b.z + a.w * b.w;
    }
    acc = warpSum(acc);
    if (lane == 0) g_x[row] = fmaxf(acc + bc[row], 0.f);
}

// K5: GRU cell; block per h, 6 warps = 6 dot rows (MLP 8/lane). 1024 x 192
__global__ void k_gru(const float* __restrict__ wih, const float* __restrict__ whh,
                      const float* __restrict__ bih, const float* __restrict__ bhh,
                      const float* __restrict__ hid, float* __restrict__ out_h) {
    __shared__ float4 xs[H / 4], hs[H / 4];
    __shared__ float dsum[6];
    int t = threadIdx.x;
    for (int i = t; i < H / 4; i += 192) {
        xs[i] = ((const float4*)g_x)[i];
        hs[i] = ((const float4*)hid)[i];
    }
    __syncthreads();
    int warp = t / 32, lane = t & 31;
    int h = blockIdx.x;
    int g = warp % 3;
    bool is_ih = warp < 3;
    const float* base = is_ih ? wih : whh;
    const float4* w4 = (const float4*)(base + ((size_t)g * H + h) * H);
    const float4* v = is_ih ? xs : hs;
    float acc = 0.f;
    #pragma unroll
    for (int k = 0; k < 8; k++) {
        float4 a = w4[lane + 32 * k], b = v[lane + 32 * k];
        acc += a.x * b.x + a.y * b.y + a.z * b.z + a.w * b.w;
    }
    acc = warpSum(acc);
    if (lane == 0) dsum[warp] = acc;
    __syncthreads();
    if (t == 0) {
        float r = 1.f / (1.f + expf(-(dsum[0] + bih[h]         + dsum[3] + bhh[h])));
        float z = 1.f / (1.f + expf(-(dsum[1] + bih[H + h]     + dsum[4] + bhh[H + h])));
        float n = tanhf(dsum[2] + bih[2 * H + h] + r * (dsum[5] + bhh[2 * H + h]));
        float hn = (1.f - z) * n + z * hid[h];
        g_h[h] = hn;
        out_h[h] = hn;
    }
}

// K6: logits + per-block partial logsumexp; warp-per-row, 8 rows/block
__global__ void __launch_bounds__(256) k_logits(const float* __restrict__ ow,
                                                const float* __restrict__ ob) {
    __shared__ float4 hs[H / 4];
    __shared__ float lg[8];
    int t = threadIdx.x;
    hs[t] = ((const float4*)g_h)[t];
    __syncthreads();
    int warp = t >> 5, lane = t & 31;
    int v = blockIdx.x * 8 + warp;
    float logit = -INFINITY;
    if (v < V) {
        const float4* w4 = (const float4*)(ow + (size_t)v * H);
        float acc = 0.f;
        #pragma unroll
        for (int k = 0; k < 8; k++) {
            float4 a = w4[lane + 32 * k];
            float4 b = hs[lane + 32 * k];
            acc += a.x * b.x + a.y * b.y + a.z * b.z + a.w * b.w;
        }
        acc = warpSum(acc);
        if (lane == 0) {
            logit = acc + ob[v];
            g_logits[v] = logit;
        }
    }
    if (lane == 0) lg[warp] = logit;
    __syncthreads();
    if (t == 0) {
        float m = -INFINITY;
        #pragma unroll
        for (int i = 0; i < 8; i++) m = fmaxf(m, lg[i]);
        float s = 0.f;
        #pragma unroll
        for (int i = 0; i < 8; i++) s += (lg[i] == -INFINITY) ? 0.f : expf(lg[i] - m);
        g_pm[blockIdx.x] = m;
        g_ps[blockIdx.x] = s;
    }
}

// K7: fused LSE-combine (redundant per block, from L2) + logp write. 99 x 512
__global__ void k_logp(float* __restrict__ out) {
    __shared__ float sm[16], ss[16];
    __shared__ float bM, bLS;
    int t = threadIdx.x;
    float m = -INFINITY, s = 0.f;
    for (int i = t; i < NB_LOGIT; i += 512) {
        float bm = g_pm[i], bs = g_ps[i];
        float nm = fmaxf(m, bm);
        s = s * expf(m - nm) + bs * expf(bm - nm);
        m = nm;
    }
    #pragma unroll
    for (int o = 16; o; o >>= 1) {
        float om = __shfl_xor_sync(0xffffffffu, m, o);
        float os = __shfl_xor_sync(0xffffffffu, s, o);
        float nm = fmaxf(m, om);
        s = s * expf(m - nm) + os * expf(om - nm);
        m = nm;
    }
    if ((t & 31) == 0) { sm[t >> 5] = m; ss[t >> 5] = s; }
    __syncthreads();
    if (t == 0) {
        float M = sm[0], S = ss[0];
        #pragma unroll
        for (int i = 1; i < 16; i++) {
            float nm = fmaxf(M, sm[i]);
            S = S * expf(M - nm) + ss[i] * expf(sm[i] - nm);
            M = nm;
        }
        bM = M;
        bLS = logf(S);
    }
    __syncthreads();
    float M = bM, LS = bLS;
    for (int v = blockIdx.x * 512 + t; v < V; v += gridDim.x * 512)
        out[v] = g_logits[v] - M - LS;
}

extern "C" void kernel_launch(void* const* d_in, const int* in_sizes, int n_in,
                              void* d_out, int out_size) {
    const long long* tok = (const long long*)d_in[0];  // int64 token id
    const float* hid  = (const float*)d_in[1];   // (1,1,H)
    const float* enc  = (const float*)d_in[2];   // (L,1,H)
    const float* emb  = (const float*)d_in[3];   // (V,H)
    const float* wc   = (const float*)d_in[4];   // (H,2H)
    const float* bc   = (const float*)d_in[5];   // (H,)
    const float* wih  = (const float*)d_in[6];   // (3H,H)
    const float* whh  = (const float*)d_in[7];   // (3H,H)
    const float* bih  = (const float*)d_in[8];   // (3H,)
    const float* bhh  = (const float*)d_in[9];   // (3H,)
    const float* ow   = (const float*)d_in[10];  // (V,H)
    const float* ob   = (const float*)d_in[11];  // (V,)

    float* out = (float*)d_out;
    float* out_logp = out;            // [0, V)
    float* out_h    = out + V;        // [V, V+H)
    float* out_attn = out + V + H;    // [V+H, V+H+L)

    k_scores<<<L / 8, 256>>>(hid, enc);
    k_attnps<<<4 * NLC, 256>>>(enc, out_attn);
    k_attnr<<<H / 256, 256>>>(emb, tok);
    k_combine<<<H / 8, 256>>>(wc, bc);
    k_gru<<<H, 192>>>(wih, whh, bih, bhh, hid, out_h);
    k_logits<<<NB_LOGIT, 256>>>(ow, ob);
    k_logp<<<99, 512>>>(out_logp);
}

// round 7
// speedup vs baseline: 1.0068x; 1.0068x over previous
#include <cuda_runtime.h>
#include <math.h>

#define H 1024
#define V 50257
#define L 512
#define NB16 ((V + 15) / 16)     // 3142 blocks of 16 rows in k_logits
#define NLC 16                   // l-chunks in attn-apply partial stage

// ---------------- scratch (device globals; no allocations allowed) ----------
__device__ float g_s[L];              // raw attention scores
__device__ float g_part[NLC * H];     // partial attn_applied sums
__device__ float g_comb[2 * H];       // [embedded | attn_applied]
__device__ float g_x[H];              // relu(combined @ Wc^T + bc)
__device__ float g_h[H];              // h_new
__device__ float g_logits[V];
__device__ float g_pm[NB16];          // per-block max
__device__ float g_ps[NB16];          // per-block sum exp

__inline__ __device__ float warpSum(float v) {
    #pragma unroll
    for (int o = 16; o; o >>= 1) v += __shfl_xor_sync(0xffffffffu, v, o);
    return v;
}
__inline__ __device__ float warpMax(float v) {
    #pragma unroll
    for (int o = 16; o; o >>= 1) v = fmaxf(v, __shfl_xor_sync(0xffffffffu, v, o));
    return v;
}

// K1: s[l] = dot(h0, enc[l]); warp-per-row, 64 blocks x 256
__global__ void k_scores(const float* __restrict__ hid, const float* __restrict__ enc) {
    __shared__ float4 hs[H / 4];
    int t = threadIdx.x;
    hs[t] = ((const float4*)hid)[t];
    __syncthreads();
    int warp = t >> 5, lane = t & 31;
    int l = blockIdx.x * 8 + warp;
    const float4* e4 = (const float4*)(enc + (size_t)l * H);
    float acc = 0.f;
    #pragma unroll
    for (int k = 0; k < 8; k++) {
        float4 a = e4[lane + 32 * k], b = hs[lane + 32 * k];
        acc += a.x * b.x + a.y * b.y + a.z * b.z + a.w * b.w;
    }
    acc = warpSum(acc);
    if (lane == 0) g_s[l] = acc;
}

// K2: fused softmax (recomputed per block from g_s) + partial attn apply.
// grid 64 = 4 h-chunks x 16 l-chunks; block 256.
__global__ void k_attnps(const float* __restrict__ enc, float* __restrict__ out_attn) {
    __shared__ float ws[L];
    __shared__ float red[8];
    __shared__ float bcast;
    int t = threadIdx.x;
    int hc = blockIdx.x & 3;
    int lc = blockIdx.x >> 2;

    float s0 = g_s[t], s1 = g_s[t + 256];
    float m = warpMax(fmaxf(s0, s1));
    if ((t & 31) == 0) red[t >> 5] = m;
    __syncthreads();
    if (t == 0) {
        float mm = red[0];
        #pragma unroll
        for (int i = 1; i < 8; i++) mm = fmaxf(mm, red[i]);
        bcast = mm;
    }
    __syncthreads();
    float M = bcast;
    float e0 = expf(s0 - M), e1 = expf(s1 - M);
    __syncthreads();
    float s = warpSum(e0 + e1);
    if ((t & 31) == 0) red[t >> 5] = s;
    __syncthreads();
    if (t == 0) {
        float ss = 0.f;
        #pragma unroll
        for (int i = 0; i < 8; i++) ss += red[i];
        bcast = 1.f / ss;
    }
    __syncthreads();
    float inv = bcast;
    ws[t] = e0 * inv;
    ws[t + 256] = e1 * inv;
    __syncthreads();

    if (hc == 0 && t < 32) out_attn[lc * 32 + t] = ws[lc * 32 + t];

    int h = hc * 256 + t;
    const float* ep = enc + (size_t)(lc * 32) * H + h;
    float acc = 0.f;
    #pragma unroll
    for (int l = 0; l < 32; l++) acc += ws[lc * 32 + l] * ep[(size_t)l * H];
    g_part[lc * H + h] = acc;
}

// K3: reduce partials -> combined[H..2H); embedded gather -> combined[0..H)
__global__ void k_attnr(const float* __restrict__ emb, const long long* __restrict__ tok) {
    int h = blockIdx.x * 256 + threadIdx.x;
    float a = 0.f;
    #pragma unroll
    for (int i = 0; i < NLC; i++) a += g_part[i * H + h];
    g_comb[H + h] = a;
    g_comb[h] = emb[(size_t)tok[0] * H + h];
}

// K4: x[row] = relu(dot(Wc[row], combined)+bc); split-K x2: 256 blocks x 256,
// 8 warps = 4 rows x 2 half-rows (8 float4 loads each).
__global__ void __launch_bounds__(256) k_combine(const float* __restrict__ wc,
                                                 const float* __restrict__ bc) {
    __shared__ float4 cs[2 * H / 4];
    __shared__ float psum[4][2];
    int t = threadIdx.x;
    cs[t] = ((const float4*)g_comb)[t];
    cs[t + 256] = ((const float4*)g_comb)[t + 256];
    __syncthreads();
    int warp = t >> 5, lane = t & 31;
    int row = blockIdx.x * 4 + (warp >> 1);
    int half = warp & 1;
    const float4* w4 = (const float4*)(wc + (size_t)row * 2 * H) + half * 256;
    const float4* c4 = cs + half * 256;
    float acc = 0.f;
    #pragma unroll
    for (int k = 0; k < 8; k++) {
        float4 a = w4[lane + 32 * k], b = c4[lane + 32 * k];
        acc += a.x * b.x + a.y * b.y + a.z * b.z + a.w * b.w;
    }
    acc = warpSum(acc);
    if (lane == 0) psum[warp >> 1][half] = acc;
    __syncthreads();
    if (t < 4) {
        int r = blockIdx.x * 4 + t;
        g_x[r] = fmaxf(psum[t][0] + psum[t][1] + bc[r], 0.f);
    }
}

// K5: GRU cell; block per h, 6 warps = 6 dot rows. 1024 x 192
__global__ void k_gru(const float* __restrict__ wih, const float* __restrict__ whh,
                      const float* __restrict__ bih, const float* __restrict__ bhh,
                      const float* __restrict__ hid, float* __restrict__ out_h) {
    __shared__ float4 xs[H / 4], hs[H / 4];
    __shared__ float dsum[6];
    int t = threadIdx.x;
    for (int i = t; i < H / 4; i += 192) {
        xs[i] = ((const float4*)g_x)[i];
        hs[i] = ((const float4*)hid)[i];
    }
    __syncthreads();
    int warp = t / 32, lane = t & 31;
    int h = blockIdx.x;
    int g = warp % 3;
    bool is_ih = warp < 3;
    const float* base = is_ih ? wih : whh;
    const float4* w4 = (const float4*)(base + ((size_t)g * H + h) * H);
    const float4* v = is_ih ? xs : hs;
    float acc = 0.f;
    #pragma unroll
    for (int k = 0; k < 8; k++) {
        float4 a = w4[lane + 32 * k], b = v[lane + 32 * k];
        acc += a.x * b.x + a.y * b.y + a.z * b.z + a.w * b.w;
    }
    acc = warpSum(acc);
    if (lane == 0) dsum[warp] = acc;
    __syncthreads();
    if (t == 0) {
        float r = 1.f / (1.f + expf(-(dsum[0] + bih[h]         + dsum[3] + bhh[h])));
        float z = 1.f / (1.f + expf(-(dsum[1] + bih[H + h]     + dsum[4] + bhh[H + h])));
        float n = tanhf(dsum[2] + bih[2 * H + h] + r * (dsum[5] + bhh[2 * H + h]));
        float hn = (1.f - z) * n + z * hid[h];
        g_h[h] = hn;
        out_h[h] = hn;
    }
}

// K6: logits + per-block partial logsumexp; 2 rows per warp, 16 rows/block.
__global__ void __launch_bounds__(256) k_logits(const float* __restrict__ ow,
                                                const float* __restrict__ ob) {
    __shared__ float4 hs[H / 4];
    __shared__ float lg[16];
    int t = threadIdx.x;
    hs[t] = ((const float4*)g_h)[t];
    __syncthreads();
    int warp = t >> 5, lane = t & 31;
    int v0 = blockIdx.x * 16 + warp * 2;   // rows v0, v0+1
    float l0 = -INFINITY, l1 = -INFINITY;
    bool r0 = v0 < V, r1 = (v0 + 1) < V;
    const float4* w0 = (const float4*)(ow + (size_t)v0 * H);
    const float4* w1 = (const float4*)(ow + (size_t)(v0 + 1) * H);
    float acc0 = 0.f, acc1 = 0.f;
    if (r1) {
        #pragma unroll
        for (int k = 0; k < 8; k++) {
            float4 b = hs[lane + 32 * k];
            float4 a0 = w0[lane + 32 * k];
            float4 a1 = w1[lane + 32 * k];
            acc0 += a0.x * b.x + a0.y * b.y + a0.z * b.z + a0.w * b.w;
            acc1 += a1.x * b.x + a1.y * b.y + a1.z * b.z + a1.w * b.w;
        }
    } else if (r0) {
        #pragma unroll
        for (int k = 0; k < 8; k++) {
            float4 b = hs[lane + 32 * k];
            float4 a0 = w0[lane + 32 * k];
            acc0 += a0.x * b.x + a0.y * b.y + a0.z * b.z + a0.w * b.w;
        }
    }
    acc0 = warpSum(acc0);
    acc1 = warpSum(acc1);
    if (lane == 0) {
        if (r0) { l0 = acc0 + ob[v0];     g_logits[v0] = l0; }
        if (r1) { l1 = acc1 + ob[v0 + 1]; g_logits[v0 + 1] = l1; }
        lg[warp * 2]     = l0;
        lg[warp * 2 + 1] = l1;
    }
    __syncthreads();
    if (t == 0) {
        float m = -INFINITY;
        #pragma unroll
        for (int i = 0; i < 16; i++) m = fmaxf(m, lg[i]);
        float s = 0.f;
        #pragma unroll
        for (int i = 0; i < 16; i++) s += (lg[i] == -INFINITY) ? 0.f : expf(lg[i] - m);
        g_pm[blockIdx.x] = m;
        g_ps[blockIdx.x] = s;
    }
}

// K7: fused LSE-combine (redundant per block, from L2) + logp write. 99 x 512
__global__ void k_logp(float* __restrict__ out) {
    __shared__ float sm[16], ss[16];
    __shared__ float bM, bLS;
    int t = threadIdx.x;
    float m = -INFINITY, s = 0.f;
    for (int i = t; i < NB16; i += 512) {
        float bm = g_pm[i], bs = g_ps[i];
        float nm = fmaxf(m, bm);
        s = s * expf(m - nm) + bs * expf(bm - nm);
        m = nm;
    }
    #pragma unroll
    for (int o = 16; o; o >>= 1) {
        float om = __shfl_xor_sync(0xffffffffu, m, o);
        float os = __shfl_xor_sync(0xffffffffu, s, o);
        float nm = fmaxf(m, om);
        s = s * expf(m - nm) + os * expf(om - nm);
        m = nm;
    }
    if ((t & 31) == 0) { sm[t >> 5] = m; ss[t >> 5] = s; }
    __syncthreads();
    if (t == 0) {
        float M = sm[0], S = ss[0];
        #pragma unroll
        for (int i = 1; i < 16; i++) {
            float nm = fmaxf(M, sm[i]);
            S = S * expf(M - nm) + ss[i] * expf(sm[i] - nm);
            M = nm;
        }
        bM = M;
        bLS = logf(S);
    }
    __syncthreads();
    float M = bM, LS = bLS;
    for (int v = blockIdx.x * 512 + t; v < V; v += gridDim.x * 512)
        out[v] = g_logits[v] - M - LS;
}

extern "C" void kernel_launch(void* const* d_in, const int* in_sizes, int n_in,
                              void* d_out, int out_size) {
    const long long* tok = (const long long*)d_in[0];  // int64 token id
    const float* hid  = (const float*)d_in[1];   // (1,1,H)
    const float* enc  = (const float*)d_in[2];   // (L,1,H)
    const float* emb  = (const float*)d_in[3];   // (V,H)
    const float* wc   = (const float*)d_in[4];   // (H,2H)
    const float* bc   = (const float*)d_in[5];   // (H,)
    const float* wih  = (const float*)d_in[6];   // (3H,H)
    const float* whh  = (const float*)d_in[7];   // (3H,H)
    const float* bih  = (const float*)d_in[8];   // (3H,)
    const float* bhh  = (const float*)d_in[9];   // (3H,)
    const float* ow   = (const float*)d_in[10];  // (V,H)
    const float* ob   = (const float*)d_in[11];  // (V,)

    float* out = (float*)d_out;
    float* out_logp = out;            // [0, V)
    float* out_h    = out + V;        // [V, V+H)
    float* out_attn = out + V + H;    // [V+H, V+H+L)

    k_scores<<<L / 8, 256>>>(hid, enc);
    k_attnps<<<4 * NLC, 256>>>(enc, out_attn);
    k_attnr<<<H / 256, 256>>>(emb, tok);
    k_combine<<<H / 4, 256>>>(wc, bc);
    k_gru<<<H, 192>>>(wih, whh, bih, bhh, hid, out_h);
    k_logits<<<NB16, 256>>>(ow, ob);
    k_logp<<<99, 512>>>(out_logp);
}

// round 8
// speedup vs baseline: 1.0347x; 1.0278x over previous
#include <cuda_runtime.h>
#include <math.h>

#define H 1024
#define V 50257
#define L 512
#define NB16 ((V + 15) / 16)     // 3142 blocks of 16 rows in k_logits
#define NLC 16                   // l-chunks in attn-apply partial stage

// ---------------- scratch (device globals; no allocations allowed) ----------
__device__ float g_s[L];              // raw attention scores
__device__ float g_part[NLC * H];     // partial attn_applied sums
__device__ float g_comb[2 * H];       // [embedded | attn_applied]
__device__ float g_x[H];              // relu(combined @ Wc^T + bc)
__device__ float g_h[H];              // h_new
__device__ float g_logits[V];
__device__ float g_pm[NB16];          // per-block max
__device__ float g_ps[NB16];          // per-block sum exp

__inline__ __device__ float warpSum(float v) {
    #pragma unroll
    for (int o = 16; o; o >>= 1) v += __shfl_xor_sync(0xffffffffu, v, o);
    return v;
}
__inline__ __device__ float warpMax(float v) {
    #pragma unroll
    for (int o = 16; o; o >>= 1) v = fmaxf(v, __shfl_xor_sync(0xffffffffu, v, o));
    return v;
}

// K1: s[l] = dot(h0, enc[l]); warp-per-row, 64 blocks x 256
__global__ void k_scores(const float* __restrict__ hid, const float* __restrict__ enc) {
    __shared__ float4 hs[H / 4];
    int t = threadIdx.x;
    hs[t] = ((const float4*)hid)[t];
    __syncthreads();
    int warp = t >> 5, lane = t & 31;
    int l = blockIdx.x * 8 + warp;
    const float4* e4 = (const float4*)(enc + (size_t)l * H);
    float acc = 0.f;
    #pragma unroll
    for (int k = 0; k < 8; k++) {
        float4 a = e4[lane + 32 * k], b = hs[lane + 32 * k];
        acc += a.x * b.x + a.y * b.y + a.z * b.z + a.w * b.w;
    }
    acc = warpSum(acc);
    if (lane == 0) g_s[l] = acc;
}

// K2: fused softmax (recomputed per block from g_s) + partial attn apply.
// grid 64 = 4 h-chunks x 16 l-chunks; block 256.
__global__ void k_attnps(const float* __restrict__ enc, float* __restrict__ out_attn) {
    __shared__ float ws[L];
    __shared__ float red[8];
    __shared__ float bcast;
    int t = threadIdx.x;
    int hc = blockIdx.x & 3;
    int lc = blockIdx.x >> 2;

    float s0 = g_s[t], s1 = g_s[t + 256];
    float m = warpMax(fmaxf(s0, s1));
    if ((t & 31) == 0) red[t >> 5] = m;
    __syncthreads();
    if (t == 0) {
        float mm = red[0];
        #pragma unroll
        for (int i = 1; i < 8; i++) mm = fmaxf(mm, red[i]);
        bcast = mm;
    }
    __syncthreads();
    float M = bcast;
    float e0 = expf(s0 - M), e1 = expf(s1 - M);
    __syncthreads();
    float s = warpSum(e0 + e1);
    if ((t & 31) == 0) red[t >> 5] = s;
    __syncthreads();
    if (t == 0) {
        float ss = 0.f;
        #pragma unroll
        for (int i = 0; i < 8; i++) ss += red[i];
        bcast = 1.f / ss;
    }
    __syncthreads();
    float inv = bcast;
    ws[t] = e0 * inv;
    ws[t + 256] = e1 * inv;
    __syncthreads();

    if (hc == 0 && t < 32) out_attn[lc * 32 + t] = ws[lc * 32 + t];

    int h = hc * 256 + t;
    const float* ep = enc + (size_t)(lc * 32) * H + h;
    float acc = 0.f;
    #pragma unroll
    for (int l = 0; l < 32; l++) acc += ws[lc * 32 + l] * ep[(size_t)l * H];
    g_part[lc * H + h] = acc;
}

// K3: reduce partials -> combined[H..2H); embedded gather -> combined[0..H)
__global__ void k_attnr(const float* __restrict__ emb, const long long* __restrict__ tok) {
    int h = blockIdx.x * 256 + threadIdx.x;
    float a = 0.f;
    #pragma unroll
    for (int i = 0; i < NLC; i++) a += g_part[i * H + h];
    g_comb[H + h] = a;
    g_comb[h] = emb[(size_t)tok[0] * H + h];
}

// K4: x[row] = relu(dot(Wc[row], combined)+bc); split-K x2: 256 blocks x 256,
// 8 warps = 4 rows x 2 half-rows (8 float4 loads each).
__global__ void __launch_bounds__(256) k_combine(const float* __restrict__ wc,
                                                 const float* __restrict__ bc) {
    __shared__ float4 cs[2 * H / 4];
    __shared__ float psum[4][2];
    int t = threadIdx.x;
    cs[t] = ((const float4*)g_comb)[t];
    cs[t + 256] = ((const float4*)g_comb)[t + 256];
    __syncthreads();
    int warp = t >> 5, lane = t & 31;
    int row = blockIdx.x * 4 + (warp >> 1);
    int half = warp & 1;
    const float4* w4 = (const float4*)(wc + (size_t)row * 2 * H) + half * 256;
    const float4* c4 = cs + half * 256;
    float acc = 0.f;
    #pragma unroll
    for (int k = 0; k < 8; k++) {
        float4 a = w4[lane + 32 * k], b = c4[lane + 32 * k];
        acc += a.x * b.x + a.y * b.y + a.z * b.z + a.w * b.w;
    }
    acc = warpSum(acc);
    if (lane == 0) psum[warp >> 1][half] = acc;
    __syncthreads();
    if (t < 4) {
        int r = blockIdx.x * 4 + t;
        g_x[r] = fmaxf(psum[t][0] + psum[t][1] + bc[r], 0.f);
    }
}

// K5: GRU cell; block per h, 6 warps = 6 dot rows. 1024 x 192
__global__ void k_gru(const float* __restrict__ wih, const float* __restrict__ whh,
                      const float* __restrict__ bih, const float* __restrict__ bhh,
                      const float* __restrict__ hid, float* __restrict__ out_h) {
    __shared__ float4 xs[H / 4], hs[H / 4];
    __shared__ float dsum[6];
    int t = threadIdx.x;
    for (int i = t; i < H / 4; i += 192) {
        xs[i] = ((const float4*)g_x)[i];
        hs[i] = ((const float4*)hid)[i];
    }
    __syncthreads();
    int warp = t / 32, lane = t & 31;
    int h = blockIdx.x;
    int g = warp % 3;
    bool is_ih = warp < 3;
    const float* base = is_ih ? wih : whh;
    const float4* w4 = (const float4*)(base + ((size_t)g * H + h) * H);
    const float4* v = is_ih ? xs : hs;
    float acc = 0.f;
    #pragma unroll
    for (int k = 0; k < 8; k++) {
        float4 a = w4[lane + 32 * k], b = v[lane + 32 * k];
        acc += a.x * b.x + a.y * b.y + a.z * b.z + a.w * b.w;
    }
    acc = warpSum(acc);
    if (lane == 0) dsum[warp] = acc;
    __syncthreads();
    if (t == 0) {
        float r = 1.f / (1.f + expf(-(dsum[0] + bih[h]         + dsum[3] + bhh[h])));
        float z = 1.f / (1.f + expf(-(dsum[1] + bih[H + h]     + dsum[4] + bhh[H + h])));
        float n = tanhf(dsum[2] + bih[2 * H + h] + r * (dsum[5] + bhh[2 * H + h]));
        float hn = (1.f - z) * n + z * hid[h];
        g_h[h] = hn;
        out_h[h] = hn;
    }
}

// K6: logits + per-block partial logsumexp; 2 rows per warp, 16 rows/block.
__global__ void __launch_bounds__(256) k_logits(const float* __restrict__ ow,
                                                const float* __restrict__ ob) {
    __shared__ float4 hs[H / 4];
    __shared__ float lg[16];
    int t = threadIdx.x;
    hs[t] = ((const float4*)g_h)[t];
    __syncthreads();
    int warp = t >> 5, lane = t & 31;
    int v0 = blockIdx.x * 16 + warp * 2;   // rows v0, v0+1
    float l0 = -INFINITY, l1 = -INFINITY;
    bool r0 = v0 < V, r1 = (v0 + 1) < V;
    const float4* w0 = (const float4*)(ow + (size_t)v0 * H);
    const float4* w1 = (const float4*)(ow + (size_t)(v0 + 1) * H);
    float acc0 = 0.f, acc1 = 0.f;
    if (r1) {
        #pragma unroll
        for (int k = 0; k < 8; k++) {
            float4 b = hs[lane + 32 * k];
            float4 a0 = w0[lane + 32 * k];
            float4 a1 = w1[lane + 32 * k];
            acc0 += a0.x * b.x + a0.y * b.y + a0.z * b.z + a0.w * b.w;
            acc1 += a1.x * b.x + a1.y * b.y + a1.z * b.z + a1.w * b.w;
        }
    } else if (r0) {
        #pragma unroll
        for (int k = 0; k < 8; k++) {
            float4 b = hs[lane + 32 * k];
            float4 a0 = w0[lane + 32 * k];
            acc0 += a0.x * b.x + a0.y * b.y + a0.z * b.z + a0.w * b.w;
        }
    }
    acc0 = warpSum(acc0);
    acc1 = warpSum(acc1);
    if (lane == 0) {
        if (r0) { l0 = acc0 + ob[v0];     g_logits[v0] = l0; }
        if (r1) { l1 = acc1 + ob[v0 + 1]; g_logits[v0 + 1] = l1; }
        lg[warp * 2]     = l0;
        lg[warp * 2 + 1] = l1;
    }
    __syncthreads();
    if (t == 0) {
        float m = -INFINITY;
        #pragma unroll
        for (int i = 0; i < 16; i++) m = fmaxf(m, lg[i]);
        float s = 0.f;
        #pragma unroll
        for (int i = 0; i < 16; i++) s += (lg[i] == -INFINITY) ? 0.f : expf(lg[i] - m);
        g_pm[blockIdx.x] = m;
        g_ps[blockIdx.x] = s;
    }
}

// K7: fused LSE-combine (redundant per block, from L2) + logp write. 99 x 512
__global__ void k_logp(float* __restrict__ out) {
    __shared__ float sm[16], ss[16];
    __shared__ float bM, bLS;
    int t = threadIdx.x;
    float m = -INFINITY, s = 0.f;
    for (int i = t; i < NB16; i += 512) {
        float bm = g_pm[i], bs = g_ps[i];
        float nm = fmaxf(m, bm);
        s = s * expf(m - nm) + bs * expf(bm - nm);
        m = nm;
    }
    #pragma unroll
    for (int o = 16; o; o >>= 1) {
        float om = __shfl_xor_sync(0xffffffffu, m, o);
        float os = __shfl_xor_sync(0xffffffffu, s, o);
        float nm = fmaxf(m, om);
        s = s * expf(m - nm) + os * expf(om - nm);
        m = nm;
    }
    if ((t & 31) == 0) { sm[t >> 5] = m; ss[t >> 5] = s; }
    __syncthreads();
    if (t == 0) {
        float M = sm[0], S = ss[0];
        #pragma unroll
        for (int i = 1; i < 16; i++) {
            float nm = fmaxf(M, sm[i]);
            S = S * expf(M - nm) + ss[i] * expf(sm[i] - nm);
            M = nm;
        }
        bM = M;
        bLS = logf(S);
    }
    __syncthreads();
    float M = bM, LS = bLS;
    for (int v = blockIdx.x * 512 + t; v < V; v += gridDim.x * 512)
        out[v] = g_logits[v] - M - LS;
}

extern "C" void kernel_launch(void* const* d_in, const int* in_sizes, int n_in,
                              void* d_out, int out_size) {
    const long long* tok = (const long long*)d_in[0];  // int64 token id
    const float* hid  = (const float*)d_in[1];   // (1,1,H)
    const float* enc  = (const float*)d_in[2];   // (L,1,H)
    const float* emb  = (const float*)d_in[3];   // (V,H)
    const float* wc   = (const float*)d_in[4];   // (H,2H)
    const float* bc   = (const float*)d_in[5];   // (H,)
    const float* wih  = (const float*)d_in[6];   // (3H,H)
    const float* whh  = (const float*)d_in[7];   // (3H,H)
    const float* bih  = (const float*)d_in[8];   // (3H,)
    const float* bhh  = (const float*)d_in[9];   // (3H,)
    const float* ow   = (const float*)d_in[10];  // (V,H)
    const float* ob   = (const float*)d_in[11];  // (V,)

    float* out = (float*)d_out;
    float* out_logp = out;            // [0, V)
    float* out_h    = out + V;        // [V, V+H)
    float* out_attn = out + V + H;    // [V+H, V+H+L)

    k_scores<<<L / 8, 256>>>(hid, enc);
    k_attnps<<<4 * NLC, 256>>>(enc, out_attn);
    k_attnr<<<H / 256, 256>>>(emb, tok);
    k_combine<<<H / 4, 256>>>(wc, bc);
    k_gru<<<H, 192>>>(wih, whh, bih, bhh, hid, out_h);
    k_logits<<<NB16, 256>>>(ow, ob);
    k_logp<<<99, 512>>>(out_logp);
}